// round 14
// baseline (speedup 1.0000x reference)
#include <cuda_runtime.h>
#include <math.h>
#include <stdint.h>

// Problem dims
#define B_   4
#define CIN  256
#define CO   128
#define HIN  64
#define WIN  64
#define H2   128
#define W2   128
#define HW2  (H2 * W2)

// Scratch (device globals)
__device__ float                   g_y[B_ * CO * H2 * W2];   // conv-transpose output
__device__ float                   g_d2[4 * B_ * 9 * HW2];   // partial sum-of-squares
__device__ float                   g_kf[B_ * 9 * HW2];       // combined adaptive factors
__device__ __align__(256) uint32_t g_w1s[4 * 4 * 8 * 4096];  // conv1 A tiles [pq][t][cch]
__device__ __align__(256) uint32_t g_w2s[9 * 4 * 4096];      // pac A tiles [t][cch]

// ---------------------------------------------------------------------------
// helpers
// ---------------------------------------------------------------------------
__device__ __forceinline__ uint32_t f2tf32(float v) {
    uint32_t o;
    asm("cvt.rn.tf32.f32 %0, %1;" : "=r"(o) : "f"(v));
    return o;
}
__device__ __forceinline__ uint32_t s32(const void* p) {
    uint32_t a;
    asm("{ .reg .u64 t; cvta.to.shared.u64 t, %1; cvt.u32.u64 %0, t; }" : "=r"(a) : "l"(p));
    return a;
}
__device__ __forceinline__ void cp_async16(uint32_t saddr, const void* gptr) {
    asm volatile("cp.async.cg.shared.global [%0], [%1], 16;" :: "r"(saddr), "l"(gptr));
}
__device__ __forceinline__ void cp_commit() { asm volatile("cp.async.commit_group;"); }
__device__ __forceinline__ void cp_wait0()  { asm volatile("cp.async.wait_group 0;" ::: "memory"); }

__device__ __forceinline__ void mma_tf32(float* d, const uint32_t* a, const uint32_t* b) {
    asm volatile(
        "mma.sync.aligned.m16n8k8.row.col.f32.tf32.tf32.f32 "
        "{%0,%1,%2,%3}, {%4,%5,%6,%7}, {%8,%9}, {%0,%1,%2,%3};"
        : "+f"(d[0]), "+f"(d[1]), "+f"(d[2]), "+f"(d[3])
        : "r"(a[0]), "r"(a[1]), "r"(a[2]), "r"(a[3]), "r"(b[0]), "r"(b[1]));
}
// A swizzle: phys float index within a 128x32 tile
__device__ __forceinline__ int a_idx(int co, int k) {
    return co * 32 + (((k >> 2) ^ (co & 7)) << 2) + (k & 3);
}

// ---------------------------------------------------------------------------
// prep kernels (weights -> tf32, tiled+swizzled)
// ---------------------------------------------------------------------------
__global__ void prep_w1s(const float* __restrict__ w1) {
    int idx = blockIdx.x * blockDim.x + threadIdx.x;
    if (idx >= 16 * CIN * CO) return;
    int co = idx & 127;
    int ci = (idx >> 7) & 255;
    int t  = (idx >> 15) & 3;
    int pq = idx >> 17;
    int p = pq >> 1, q = pq & 1;
    int th = t >> 1, tw = t & 1;
    int kh = (p == 0) ? (th == 0 ? 1 : 3) : (th == 0 ? 2 : 0);
    int kw = (q == 0) ? (tw == 0 ? 1 : 3) : (tw == 0 ? 2 : 0);
    float v = w1[((ci * CO + co) * 4 + kh) * 4 + kw];
    int k = ci & 31, cch = ci >> 5;
    g_w1s[(size_t)(((pq * 4 + t) * 8) + cch) * 4096 + a_idx(co, k)] = f2tf32(v);
}

__global__ void prep_w2s(const float* __restrict__ w2) {
    int idx = blockIdx.x * blockDim.x + threadIdx.x;
    if (idx >= 9 * 128 * 128) return;
    int co = idx & 127;
    int ci = (idx >> 7) & 127;
    int t  = idx >> 14;
    int di = t / 3, dj = t % 3;
    float v = w2[((ci * CO + co) * 3 + (2 - di)) * 3 + (2 - dj)];
    int k = ci & 31, cch = ci >> 5;
    g_w2s[(size_t)(t * 4 + cch) * 4096 + a_idx(co, k)] = f2tf32(v);
}

// ---------------------------------------------------------------------------
// GEMM compute step: one K=32 chunk, 8 warps (2 co-groups x 4 pix-groups)
// ---------------------------------------------------------------------------
__device__ __forceinline__ void gemm_chunk(
    const uint32_t* __restrict__ As, const uint32_t* __restrict__ Bs,
    float acc[4][4][4], int lane, int wm, int wn)
{
    const int row = lane >> 2;
    const int kk  = lane & 3;
#pragma unroll
    for (int ks = 0; ks < 4; ks++) {
        uint32_t af[4][4];
#pragma unroll
        for (int mt = 0; mt < 4; mt++) {
            int co = wm + mt * 16 + row;
            int sw0 = (((2 * ks) ^ (co & 7)) << 2);
            int sw1 = (((2 * ks + 1) ^ (co & 7)) << 2);
            af[mt][0] = As[co * 32 + sw0 + kk];
            af[mt][1] = As[(co + 8) * 32 + sw0 + kk];
            af[mt][2] = As[co * 32 + sw1 + kk];
            af[mt][3] = As[(co + 8) * 32 + sw1 + kk];
        }
        uint32_t bf[4][2];
        const int k0 = ks * 8 + kk;
        const int k1 = k0 + 4;
#pragma unroll
        for (int nt = 0; nt < 4; nt++) {
            int n = wn + nt * 8 + row;
            bf[nt][0] = Bs[k0 * 128 + (((n >> 2) ^ (k0 & 7)) << 2) + (n & 3)];
            bf[nt][1] = Bs[k1 * 128 + (((n >> 2) ^ (k1 & 7)) << 2) + (n & 3)];
        }
#pragma unroll
        for (int mt = 0; mt < 4; mt++)
#pragma unroll
            for (int nt = 0; nt < 4; nt++)
                mma_tf32(acc[mt][nt], af[mt], bf[nt]);
    }
}

// ---------------------------------------------------------------------------
// conv1: transpose-conv as per-parity tf32 MMA GEMM.
// A double-buffered (cp.async), B single-buffered; 48KB dynamic, 0 static smem.
// ---------------------------------------------------------------------------
__global__ __launch_bounds__(256) void conv1_mma(
    const float* __restrict__ x, const float* __restrict__ b1)
{
    extern __shared__ uint32_t sm[];
    uint32_t* Asb[2] = {sm, sm + 4096};
    uint32_t* Bs = sm + 8192;
    const uint32_t sbase = s32(sm);

    const int tid = threadIdx.x;
    const int lane = tid & 31, wid = tid >> 5;
    const int wm = (wid >> 2) * 64, wn = (wid & 3) * 32;
    const int pq = blockIdx.y;
    const int p = pq >> 1, q = pq & 1;
    const int b = blockIdx.z;
    const int i0 = blockIdx.x * 2;
    const int lq = lane, wq = wid;

    float acc[4][4][4];
#pragma unroll
    for (int mt = 0; mt < 4; mt++)
#pragma unroll
        for (int nt = 0; nt < 4; nt++)
#pragma unroll
            for (int r = 0; r < 4; r++) acc[mt][nt][r] = 0.f;

    const float* xb = x + (size_t)b * CIN * HIN * WIN;

    auto prefA = [&](int it, int buf) {
        const uint32_t* src = g_w1s + (size_t)((pq * 4 + (it >> 3)) * 8 + (it & 7)) * 4096;
        uint32_t dst = sbase + (uint32_t)buf * 16384u + (uint32_t)tid * 16u;
#pragma unroll
        for (int j = 0; j < 4; j++)
            cp_async16(dst + j * 4096u, src + tid * 4 + j * 1024);
        cp_commit();
    };
    auto loadB = [&](int it, uint32_t bv[16]) {
        const int t = it >> 3, cch = it & 7;
        const int th = t >> 1, tw = t & 1;
        const int di = (th == 0) ? 0 : (p == 0 ? -1 : 1);
        const int dj = (tw == 0) ? 0 : (q == 0 ? -1 : 1);
#pragma unroll
        for (int j = 0; j < 4; j++) {
            const int k = wq * 4 + j;
            const float* xrow = xb + (size_t)(cch * 32 + k) * HIN * WIN;
#pragma unroll
            for (int i = 0; i < 4; i++) {
                int pix = lq * 4 + i;
                int gr = i0 + (pix >> 6) + di;
                int gc = (pix & 63) + dj;
                float xv = 0.f;
                if ((unsigned)gr < HIN && (unsigned)gc < WIN)
                    xv = __ldg(xrow + gr * WIN + gc);
                bv[j * 4 + i] = f2tf32(xv);
            }
        }
    };
    auto storeB = [&](const uint32_t bv[16]) {
#pragma unroll
        for (int j = 0; j < 4; j++) {
            const int k = wq * 4 + j;
            uint4 v = {bv[j * 4], bv[j * 4 + 1], bv[j * 4 + 2], bv[j * 4 + 3]};
            *(uint4*)&Bs[k * 128 + ((lq ^ (k & 7)) << 2)] = v;
        }
    };

    // prologue: stage chunk 0
    {
        prefA(0, 0);
        uint32_t bv[16];
        loadB(0, bv);
        storeB(bv);
        cp_wait0();
        __syncthreads();
    }

    for (int it = 0; it < 32; it++) {
        const int cur = it & 1, nxt = cur ^ 1;
        uint32_t bv[16];
        if (it + 1 < 32) {
            prefA(it + 1, nxt);
            loadB(it + 1, bv);
        }
        gemm_chunk(Asb[cur], Bs, acc, lane, wm, wn);
        __syncthreads();                 // all warps done reading Bs
        if (it + 1 < 32) {
            storeB(bv);
            cp_wait0();
        }
        __syncthreads();                 // Bs + A(nxt) ready
    }

    // epilogue -> g_y (strided by parity)
    float* yb = g_y + (size_t)b * CO * HW2;
    const int row = lane >> 2, col2 = (lane & 3) * 2;
#pragma unroll
    for (int mt = 0; mt < 4; mt++) {
        int co = wm + mt * 16 + row;
        float bv0 = __ldg(b1 + co);
        float bv1 = __ldg(b1 + co + 8);
#pragma unroll
        for (int nt = 0; nt < 4; nt++) {
            int pix = wn + nt * 8 + col2;
            int I = i0 + (pix >> 6), j = pix & 63;
            int oh = 2 * I + p, ow = 2 * j + q;
            float* d0 = yb + (size_t)co * HW2 + oh * W2 + ow;
            d0[0] = acc[mt][nt][0] + bv0;
            d0[2] = acc[mt][nt][1] + bv0;
            float* d1 = yb + (size_t)(co + 8) * HW2 + oh * W2 + ow;
            d1[0] = acc[mt][nt][2] + bv1;
            d1[2] = acc[mt][nt][3] + bv1;
        }
    }
}

// ---------------------------------------------------------------------------
// kfac partial: sum (g_n - g)^2 over a 32-channel group; 4 groups in parallel.
// ---------------------------------------------------------------------------
__global__ __launch_bounds__(256) void kfac_partial(const float* __restrict__ guide) {
    __shared__ float gs[8][18][18];
    const int b   = blockIdx.z >> 2;
    const int grp = blockIdx.z & 3;
    const int h0 = blockIdx.y * 16, w0 = blockIdx.x * 16;
    const int tid = threadIdx.x;
    const int ly = tid >> 4, lx = tid & 15;

    float s[9];
#pragma unroll
    for (int t = 0; t < 9; t++) s[t] = 0.f;

    const float* gb = guide + (size_t)b * CO * HW2 + (size_t)grp * 32 * HW2;

    for (int c0 = 0; c0 < 32; c0 += 8) {
        for (int idx = tid; idx < 8 * 18 * 18; idx += 256) {
            int col = idx % 18;
            int tmp = idx / 18;
            int r = tmp % 18;
            int cc = tmp / 18;
            int gr = h0 - 1 + r, gc = w0 - 1 + col;
            float v = 0.f;
            if ((unsigned)gr < H2 && (unsigned)gc < W2)
                v = gb[(size_t)(c0 + cc) * HW2 + gr * W2 + gc];
            gs[cc][r][col] = v;
        }
        __syncthreads();
#pragma unroll
        for (int cc = 0; cc < 8; cc++) {
            float g0 = gs[cc][ly + 1][lx + 1];
#pragma unroll
            for (int di = 0; di < 3; di++)
#pragma unroll
                for (int dj = 0; dj < 3; dj++) {
                    float d = gs[cc][ly + di][lx + dj] - g0;
                    s[di * 3 + dj] = fmaf(d, d, s[di * 3 + dj]);
                }
        }
        __syncthreads();
    }

    const int h = h0 + ly, w = w0 + lx;
    float* db = g_d2 + ((size_t)(grp * B_ + b) * 9) * HW2;
#pragma unroll
    for (int t = 0; t < 9; t++)
        db[(size_t)t * HW2 + h * W2 + w] = s[t];
}

// ---------------------------------------------------------------------------
// kfac combine: g_kf = exp(-0.5 * sum over 4 channel-group partials)
// ---------------------------------------------------------------------------
__global__ __launch_bounds__(256) void kfac_combine() {
    const int S = B_ * 9 * HW2 / 4;   // float4 count per group
    int i = blockIdx.x * 256 + threadIdx.x;
    if (i >= S) return;
    const float4* p = (const float4*)g_d2;
    float4 a = p[i], b = p[i + S], c = p[i + 2 * S], d = p[i + 3 * S];
    float4 o;
    o.x = expf(-0.5f * (a.x + b.x + c.x + d.x));
    o.y = expf(-0.5f * (a.y + b.y + c.y + d.y));
    o.z = expf(-0.5f * (a.z + b.z + c.z + d.z));
    o.w = expf(-0.5f * (a.w + b.w + c.w + d.w));
    ((float4*)g_kf)[i] = o;
}

// ---------------------------------------------------------------------------
// pac: tf32 MMA GEMM, kf folded into B operand (read from g_kf, L1-cached).
// A double-buffered (cp.async), B single-buffered; 48KB dynamic, 0 static smem.
// ---------------------------------------------------------------------------
__global__ __launch_bounds__(256) void pac_mma(
    const float* __restrict__ b2, float* __restrict__ out)
{
    extern __shared__ uint32_t sm[];
    uint32_t* Asb[2] = {sm, sm + 4096};
    uint32_t* Bs = sm + 8192;
    const uint32_t sbase = s32(sm);

    const int tid = threadIdx.x;
    const int lane = tid & 31, wid = tid >> 5;
    const int wm = (wid >> 2) * 64, wn = (wid & 3) * 32;
    const int b = blockIdx.z;
    const int h0 = blockIdx.y * 2;
    const int w0 = blockIdx.x * 64;
    const int lq = lane, wq = wid;

    float acc[4][4][4];
#pragma unroll
    for (int mt = 0; mt < 4; mt++)
#pragma unroll
        for (int nt = 0; nt < 4; nt++)
#pragma unroll
            for (int r = 0; r < 4; r++) acc[mt][nt][r] = 0.f;

    const float* yb = g_y + (size_t)b * CO * HW2;
    const float* kfb = g_kf + (size_t)b * 9 * HW2;

    auto prefA = [&](int it, int buf) {
        const uint32_t* src = g_w2s + (size_t)((it >> 2) * 4 + (it & 3)) * 4096;
        uint32_t dst = sbase + (uint32_t)buf * 16384u + (uint32_t)tid * 16u;
#pragma unroll
        for (int j = 0; j < 4; j++)
            cp_async16(dst + j * 4096u, src + tid * 4 + j * 1024);
        cp_commit();
    };
    auto loadB = [&](int it, uint32_t bv[16]) {
        const int t = it >> 2, cch = it & 3;
        const int di = t / 3 - 1, dj = t % 3 - 1;
        const float* kfrow = kfb + (size_t)t * HW2;
        float kfv[4];
#pragma unroll
        for (int i = 0; i < 4; i++) {
            int pix = lq * 4 + i;
            kfv[i] = __ldg(kfrow + (h0 + (pix >> 6)) * W2 + w0 + (pix & 63));
        }
#pragma unroll
        for (int j = 0; j < 4; j++) {
            const int k = wq * 4 + j;
            const float* yrow = yb + (size_t)(cch * 32 + k) * HW2;
#pragma unroll
            for (int i = 0; i < 4; i++) {
                int pix = lq * 4 + i;
                int h = h0 + (pix >> 6) + di;
                int w = w0 + (pix & 63) + dj;
                float yv = 0.f;
                if ((unsigned)h < H2 && (unsigned)w < W2)
                    yv = __ldg(yrow + h * W2 + w);
                bv[j * 4 + i] = f2tf32(yv * kfv[i]);
            }
        }
    };
    auto storeB = [&](const uint32_t bv[16]) {
#pragma unroll
        for (int j = 0; j < 4; j++) {
            const int k = wq * 4 + j;
            uint4 v = {bv[j * 4], bv[j * 4 + 1], bv[j * 4 + 2], bv[j * 4 + 3]};
            *(uint4*)&Bs[k * 128 + ((lq ^ (k & 7)) << 2)] = v;
        }
    };

    // prologue
    {
        prefA(0, 0);
        uint32_t bv[16];
        loadB(0, bv);
        storeB(bv);
        cp_wait0();
        __syncthreads();
    }

    for (int it = 0; it < 36; it++) {
        const int cur = it & 1, nxt = cur ^ 1;
        uint32_t bv[16];
        if (it + 1 < 36) {
            prefA(it + 1, nxt);
            loadB(it + 1, bv);
        }
        gemm_chunk(Asb[cur], Bs, acc, lane, wm, wn);
        __syncthreads();                 // all warps done reading Bs
        if (it + 1 < 36) {
            storeB(bv);
            cp_wait0();
        }
        __syncthreads();                 // Bs + A(nxt) ready
    }

    // epilogue
    float* ob = out + (size_t)b * CO * HW2;
    const int row = lane >> 2, col2 = (lane & 3) * 2;
#pragma unroll
    for (int mt = 0; mt < 4; mt++) {
        int co = wm + mt * 16 + row;
        float bv0 = __ldg(b2 + co);
        float bv1 = __ldg(b2 + co + 8);
#pragma unroll
        for (int nt = 0; nt < 4; nt++) {
            int pix = wn + nt * 8 + col2;
            int h = h0 + (pix >> 6), w = w0 + (pix & 63);
            float2 v0 = {acc[mt][nt][0] + bv0, acc[mt][nt][1] + bv0};
            float2 v1 = {acc[mt][nt][2] + bv1, acc[mt][nt][3] + bv1};
            *(float2*)(ob + (size_t)co * HW2 + h * W2 + w) = v0;
            *(float2*)(ob + (size_t)(co + 8) * HW2 + h * W2 + w) = v1;
        }
    }
}

// ---------------------------------------------------------------------------
// 48KB dynamic smem, zero static — within default limit, no attribute calls.
#define SMEM_GEMM (16384u * 3u)

extern "C" void kernel_launch(void* const* d_in, const int* in_sizes, int n_in,
                              void* d_out, int out_size)
{
    const float* x     = (const float*)d_in[0];
    const float* guide = (const float*)d_in[1];
    const float* w1    = (const float*)d_in[2];
    const float* b1    = (const float*)d_in[3];
    const float* w2    = (const float*)d_in[4];
    const float* b2    = (const float*)d_in[5];
    float* out = (float*)d_out;

    prep_w1s<<<(16 * CIN * CO + 255) / 256, 256>>>(w1);
    prep_w2s<<<(9 * 128 * 128 + 255) / 256, 256>>>(w2);
    conv1_mma<<<dim3(32, 4, 4), 256, SMEM_GEMM>>>(x, b1);
    kfac_partial<<<dim3(8, 8, 16), 256>>>(guide);
    kfac_combine<<<(B_ * 9 * HW2 / 4 + 255) / 256, 256>>>();
    pac_mma<<<dim3(2, 64, 4), 256, SMEM_GEMM>>>(b2, out);
}

// round 15
// speedup vs baseline: 1.3185x; 1.3185x over previous
#include <cuda_runtime.h>
#include <math.h>
#include <stdint.h>

// Problem dims
#define B_   4
#define CIN  256
#define CO   128
#define HIN  64
#define WIN  64
#define H2   128
#define W2   128
#define HW2  (H2 * W2)

// Scratch (device globals)
__device__ float                   g_y[B_ * CO * H2 * W2];   // conv-transpose output
__device__ float                   g_d2[4 * B_ * 9 * HW2];   // partial sum-of-squares
__device__ float                   g_kf[B_ * 9 * HW2];       // combined adaptive factors
__device__ __align__(256) uint32_t g_w1s[4 * 4 * 8 * 4096];  // conv1 A tiles, fragment order
__device__ __align__(256) uint32_t g_w2s[9 * 4 * 4096];      // pac A tiles, fragment order

// ---------------------------------------------------------------------------
// helpers
// ---------------------------------------------------------------------------
__device__ __forceinline__ uint32_t f2tf32(float v) {
    uint32_t o;
    asm("cvt.rn.tf32.f32 %0, %1;" : "=r"(o) : "f"(v));
    return o;
}
__device__ __forceinline__ void mma_tf32(float* d, const uint32_t* a, const uint32_t* b) {
    asm volatile(
        "mma.sync.aligned.m16n8k8.row.col.f32.tf32.tf32.f32 "
        "{%0,%1,%2,%3}, {%4,%5,%6,%7}, {%8,%9}, {%0,%1,%2,%3};"
        : "+f"(d[0]), "+f"(d[1]), "+f"(d[2]), "+f"(d[3])
        : "r"(a[0]), "r"(a[1]), "r"(a[2]), "r"(a[3]), "r"(b[0]), "r"(b[1]));
}

// Fragment-order A index (float idx within one 128x32 tile = 4096 floats):
// tile16 tg = co>>4, ks = k>>3; lane = (co&7)*4 + (k&3);
// reg = ((co>>3)&1) | (((k>>2)&1)<<1)   [matches mma a0..a3 layout]
__device__ __forceinline__ int a_frag_idx(int co, int k) {
    int tg = co >> 4, ks = k >> 3;
    int lane = ((co & 7) << 2) | (k & 3);
    int reg = ((co >> 3) & 1) | (((k >> 2) & 1) << 1);
    return (((ks * 8 + tg) * 32 + lane) << 2) | reg;
}

// ---------------------------------------------------------------------------
// prep kernels (weights -> tf32, fragment-ordered tiles)
// ---------------------------------------------------------------------------
__global__ void prep_w1s(const float* __restrict__ w1) {
    int idx = blockIdx.x * blockDim.x + threadIdx.x;
    if (idx >= 16 * CIN * CO) return;
    int co = idx & 127;
    int ci = (idx >> 7) & 255;
    int t  = (idx >> 15) & 3;
    int pq = idx >> 17;
    int p = pq >> 1, q = pq & 1;
    int th = t >> 1, tw = t & 1;
    int kh = (p == 0) ? (th == 0 ? 1 : 3) : (th == 0 ? 2 : 0);
    int kw = (q == 0) ? (tw == 0 ? 1 : 3) : (tw == 0 ? 2 : 0);
    float v = w1[((ci * CO + co) * 4 + kh) * 4 + kw];
    int k = ci & 31, cch = ci >> 5;
    g_w1s[(size_t)(((pq * 4 + t) * 8) + cch) * 4096 + a_frag_idx(co, k)] = f2tf32(v);
}

__global__ void prep_w2s(const float* __restrict__ w2) {
    int idx = blockIdx.x * blockDim.x + threadIdx.x;
    if (idx >= 9 * 128 * 128) return;
    int co = idx & 127;
    int ci = (idx >> 7) & 127;
    int t  = idx >> 14;
    int di = t / 3, dj = t % 3;
    float v = w2[((ci * CO + co) * 3 + (2 - di)) * 3 + (2 - dj)];
    int k = ci & 31, cch = ci >> 5;
    g_w2s[(size_t)(t * 4 + cch) * 4096 + a_frag_idx(co, k)] = f2tf32(v);
}

// ---------------------------------------------------------------------------
// GEMM compute: one K=32 chunk. A frags via LDS.128 (fragment-ordered tile),
// B frags via xor-swizzled LDS.32 (as before).
// ---------------------------------------------------------------------------
__device__ __forceinline__ void gemm_chunk(
    const uint32_t* __restrict__ As, const uint32_t* __restrict__ Bs,
    float acc[4][4][4], int lane, int tgbase, int wn)
{
    const int row = lane >> 2;
    const int kk  = lane & 3;
#pragma unroll
    for (int ks = 0; ks < 4; ks++) {
        uint32_t af[4][4];
#pragma unroll
        for (int mt = 0; mt < 4; mt++) {
            uint4 v = *(const uint4*)&As[((ks * 8 + tgbase + mt) * 32 + lane) << 2];
            af[mt][0] = v.x; af[mt][1] = v.y; af[mt][2] = v.z; af[mt][3] = v.w;
        }
        uint32_t bf[4][2];
        const int k0 = ks * 8 + kk;
        const int k1 = k0 + 4;
#pragma unroll
        for (int nt = 0; nt < 4; nt++) {
            int n = wn + nt * 8 + row;
            bf[nt][0] = Bs[k0 * 128 + (((n >> 2) ^ (k0 & 7)) << 2) + (n & 3)];
            bf[nt][1] = Bs[k1 * 128 + (((n >> 2) ^ (k1 & 7)) << 2) + (n & 3)];
        }
#pragma unroll
        for (int mt = 0; mt < 4; mt++)
#pragma unroll
            for (int nt = 0; nt < 4; nt++)
                mma_tf32(acc[mt][nt], af[mt], bf[nt]);
    }
}

// ---------------------------------------------------------------------------
// conv1: transpose-conv as per-parity tf32 MMA GEMM (R8 skeleton).
// ---------------------------------------------------------------------------
__global__ __launch_bounds__(256) void conv1_mma(
    const float* __restrict__ x, const float* __restrict__ b1)
{
    __shared__ __align__(16) uint32_t As[4096];
    __shared__ __align__(16) uint32_t Bs[4096];

    const int tid = threadIdx.x;
    const int lane = tid & 31, wid = tid >> 5;
    const int tgbase = (wid >> 2) * 4, wn = (wid & 3) * 32;
    const int pq = blockIdx.y;
    const int p = pq >> 1, q = pq & 1;
    const int b = blockIdx.z;
    const int i0 = blockIdx.x * 2;
    const int lq = lane, wq = wid;

    float acc[4][4][4];
#pragma unroll
    for (int mt = 0; mt < 4; mt++)
#pragma unroll
        for (int nt = 0; nt < 4; nt++)
#pragma unroll
            for (int r = 0; r < 4; r++) acc[mt][nt][r] = 0.f;

    const float* xb = x + (size_t)b * CIN * HIN * WIN;

    for (int t = 0; t < 4; t++) {
        const int th = t >> 1, tw = t & 1;
        const int di = (th == 0) ? 0 : (p == 0 ? -1 : 1);
        const int dj = (tw == 0) ? 0 : (q == 0 ? -1 : 1);
        for (int cch = 0; cch < 8; cch++) {
            // stage A: linear copy of fragment-ordered tile
            {
                const uint4* src = (const uint4*)(g_w1s + (size_t)((pq * 4 + t) * 8 + cch) * 4096);
                uint4* dst = (uint4*)As;
#pragma unroll
                for (int j = 0; j < 4; j++) dst[tid + j * 256] = src[tid + j * 256];
            }
            // stage B: tf32(x) 32ci x 128pix, xor-swizzled
            {
#pragma unroll
                for (int j = 0; j < 4; j++) {
                    const int k = wq * 4 + j;
                    const float* xrow = xb + (size_t)(cch * 32 + k) * HIN * WIN;
                    uint4 v;
                    uint32_t* vp = (uint32_t*)&v;
#pragma unroll
                    for (int i = 0; i < 4; i++) {
                        int pix = lq * 4 + i;
                        int gr = i0 + (pix >> 6) + di;
                        int gc = (pix & 63) + dj;
                        float xv = 0.f;
                        if ((unsigned)gr < HIN && (unsigned)gc < WIN)
                            xv = __ldg(xrow + gr * WIN + gc);
                        vp[i] = f2tf32(xv);
                    }
                    *(uint4*)&Bs[k * 128 + ((lq ^ (k & 7)) << 2)] = v;
                }
            }
            __syncthreads();
            gemm_chunk(As, Bs, acc, lane, tgbase, wn);
            __syncthreads();
        }
    }

    // epilogue -> g_y (strided by parity)
    float* yb = g_y + (size_t)b * CO * HW2;
    const int row = lane >> 2, col2 = (lane & 3) * 2;
#pragma unroll
    for (int mt = 0; mt < 4; mt++) {
        int co = tgbase * 16 + mt * 16 + row;
        float bv0 = __ldg(b1 + co);
        float bv1 = __ldg(b1 + co + 8);
#pragma unroll
        for (int nt = 0; nt < 4; nt++) {
            int pix = wn + nt * 8 + col2;
            int I = i0 + (pix >> 6), j = pix & 63;
            int oh = 2 * I + p, ow = 2 * j + q;
            float* d0 = yb + (size_t)co * HW2 + oh * W2 + ow;
            d0[0] = acc[mt][nt][0] + bv0;
            d0[2] = acc[mt][nt][1] + bv0;
            float* d1 = yb + (size_t)(co + 8) * HW2 + oh * W2 + ow;
            d1[0] = acc[mt][nt][2] + bv1;
            d1[2] = acc[mt][nt][3] + bv1;
        }
    }
}

// ---------------------------------------------------------------------------
// kfac partial: sum (g_n - g)^2 over a 32-channel group; 4 groups in parallel.
// ---------------------------------------------------------------------------
__global__ __launch_bounds__(256) void kfac_partial(const float* __restrict__ guide) {
    __shared__ float gs[8][18][18];
    const int b   = blockIdx.z >> 2;
    const int grp = blockIdx.z & 3;
    const int h0 = blockIdx.y * 16, w0 = blockIdx.x * 16;
    const int tid = threadIdx.x;
    const int ly = tid >> 4, lx = tid & 15;

    float s[9];
#pragma unroll
    for (int t = 0; t < 9; t++) s[t] = 0.f;

    const float* gb = guide + (size_t)b * CO * HW2 + (size_t)grp * 32 * HW2;

    for (int c0 = 0; c0 < 32; c0 += 8) {
        for (int idx = tid; idx < 8 * 18 * 18; idx += 256) {
            int col = idx % 18;
            int tmp = idx / 18;
            int r = tmp % 18;
            int cc = tmp / 18;
            int gr = h0 - 1 + r, gc = w0 - 1 + col;
            float v = 0.f;
            if ((unsigned)gr < H2 && (unsigned)gc < W2)
                v = gb[(size_t)(c0 + cc) * HW2 + gr * W2 + gc];
            gs[cc][r][col] = v;
        }
        __syncthreads();
#pragma unroll
        for (int cc = 0; cc < 8; cc++) {
            float g0 = gs[cc][ly + 1][lx + 1];
#pragma unroll
            for (int di = 0; di < 3; di++)
#pragma unroll
                for (int dj = 0; dj < 3; dj++) {
                    float d = gs[cc][ly + di][lx + dj] - g0;
                    s[di * 3 + dj] = fmaf(d, d, s[di * 3 + dj]);
                }
        }
        __syncthreads();
    }

    const int h = h0 + ly, w = w0 + lx;
    float* db = g_d2 + ((size_t)(grp * B_ + b) * 9) * HW2;
#pragma unroll
    for (int t = 0; t < 9; t++)
        db[(size_t)t * HW2 + h * W2 + w] = s[t];
}

// ---------------------------------------------------------------------------
// kfac combine: g_kf = exp(-0.5 * sum over 4 channel-group partials)
// ---------------------------------------------------------------------------
__global__ __launch_bounds__(256) void kfac_combine() {
    const int S = B_ * 9 * HW2 / 4;   // float4 count per group
    int i = blockIdx.x * 256 + threadIdx.x;
    if (i >= S) return;
    const float4* p = (const float4*)g_d2;
    float4 a = p[i], b = p[i + S], c = p[i + 2 * S], d = p[i + 3 * S];
    float4 o;
    o.x = expf(-0.5f * (a.x + b.x + c.x + d.x));
    o.y = expf(-0.5f * (a.y + b.y + c.y + d.y));
    o.z = expf(-0.5f * (a.z + b.z + c.z + d.z));
    o.w = expf(-0.5f * (a.w + b.w + c.w + d.w));
    ((float4*)g_kf)[i] = o;
}

// ---------------------------------------------------------------------------
// pac: tf32 MMA GEMM, kf folded into B operand (kfs staged in static smem).
// ---------------------------------------------------------------------------
__global__ __launch_bounds__(256) void pac_mma(
    const float* __restrict__ b2, float* __restrict__ out)
{
    __shared__ __align__(16) uint32_t As[4096];
    __shared__ __align__(16) uint32_t Bs[4096];
    __shared__ float kfs[9 * 128];

    const int tid = threadIdx.x;
    const int lane = tid & 31, wid = tid >> 5;
    const int tgbase = (wid >> 2) * 4, wn = (wid & 3) * 32;
    const int b = blockIdx.z;
    const int h0 = blockIdx.y * 2;
    const int w0 = blockIdx.x * 64;
    const int lq = lane, wq = wid;

    // stage kf for this tile (already exp'd)
    {
        const float* kb = g_kf + (size_t)b * 9 * HW2;
        for (int i = tid; i < 9 * 128; i += 256) {
            int pix = i & 127, t = i >> 7;
            kfs[i] = kb[(size_t)t * HW2 + (h0 + (pix >> 6)) * W2 + w0 + (pix & 63)];
        }
    }

    float acc[4][4][4];
#pragma unroll
    for (int mt = 0; mt < 4; mt++)
#pragma unroll
        for (int nt = 0; nt < 4; nt++)
#pragma unroll
            for (int r = 0; r < 4; r++) acc[mt][nt][r] = 0.f;

    const float* yb = g_y + (size_t)b * CO * HW2;
    __syncthreads();

    for (int t = 0; t < 9; t++) {
        const int di = t / 3 - 1, dj = t % 3 - 1;
        for (int cch = 0; cch < 4; cch++) {
            // stage A
            {
                const uint4* src = (const uint4*)(g_w2s + (size_t)(t * 4 + cch) * 4096);
                uint4* dst = (uint4*)As;
#pragma unroll
                for (int j = 0; j < 4; j++) dst[tid + j * 256] = src[tid + j * 256];
            }
            // stage B: tf32(y * kf)
            {
                float kfv[4];
#pragma unroll
                for (int i = 0; i < 4; i++) kfv[i] = kfs[t * 128 + lq * 4 + i];
#pragma unroll
                for (int j = 0; j < 4; j++) {
                    const int k = wq * 4 + j;
                    const float* yrow = yb + (size_t)(cch * 32 + k) * HW2;
                    uint4 v;
                    uint32_t* vp = (uint32_t*)&v;
#pragma unroll
                    for (int i = 0; i < 4; i++) {
                        int pix = lq * 4 + i;
                        int h = h0 + (pix >> 6) + di;
                        int w = w0 + (pix & 63) + dj;
                        float yv = 0.f;
                        if ((unsigned)h < H2 && (unsigned)w < W2)
                            yv = __ldg(yrow + h * W2 + w);
                        vp[i] = f2tf32(yv * kfv[i]);
                    }
                    *(uint4*)&Bs[k * 128 + ((lq ^ (k & 7)) << 2)] = v;
                }
            }
            __syncthreads();
            gemm_chunk(As, Bs, acc, lane, tgbase, wn);
            __syncthreads();
        }
    }

    // epilogue
    float* ob = out + (size_t)b * CO * HW2;
    const int row = lane >> 2, col2 = (lane & 3) * 2;
#pragma unroll
    for (int mt = 0; mt < 4; mt++) {
        int co = tgbase * 16 + mt * 16 + row;
        float bv0 = __ldg(b2 + co);
        float bv1 = __ldg(b2 + co + 8);
#pragma unroll
        for (int nt = 0; nt < 4; nt++) {
            int pix = wn + nt * 8 + col2;
            int h = h0 + (pix >> 6), w = w0 + (pix & 63);
            float2 v0 = {acc[mt][nt][0] + bv0, acc[mt][nt][1] + bv0};
            float2 v1 = {acc[mt][nt][2] + bv1, acc[mt][nt][3] + bv1};
            *(float2*)(ob + (size_t)co * HW2 + h * W2 + w) = v0;
            *(float2*)(ob + (size_t)(co + 8) * HW2 + h * W2 + w) = v1;
        }
    }
}

// ---------------------------------------------------------------------------
extern "C" void kernel_launch(void* const* d_in, const int* in_sizes, int n_in,
                              void* d_out, int out_size)
{
    const float* x     = (const float*)d_in[0];
    const float* guide = (const float*)d_in[1];
    const float* w1    = (const float*)d_in[2];
    const float* b1    = (const float*)d_in[3];
    const float* w2    = (const float*)d_in[4];
    const float* b2    = (const float*)d_in[5];
    float* out = (float*)d_out;

    prep_w1s<<<(16 * CIN * CO + 255) / 256, 256>>>(w1);
    prep_w2s<<<(9 * 128 * 128 + 255) / 256, 256>>>(w2);
    kfac_partial<<<dim3(8, 8, 16), 256>>>(guide);
    kfac_combine<<<(B_ * 9 * HW2 / 4 + 255) / 256, 256>>>();
    conv1_mma<<<dim3(32, 4, 4), 256>>>(x, b1);
    pac_mma<<<dim3(2, 64, 4), 256>>>(b2, out);
}